// round 4
// baseline (speedup 1.0000x reference)
#include <cuda_runtime.h>
#include <cuda_bf16.h>

#define WARPS_PER_BLOCK 8
#define THREADS (WARPS_PER_BLOCK * 32)

__device__ __forceinline__ void cmul(float& ar, float& ai, float br, float bi) {
    float r = ar * br - ai * bi;
    float i = ar * bi + ai * br;
    ar = r; ai = i;
}

__host__ __device__ constexpr int msbbit(int v) { int b = 1; while (v >>= 1) b <<= 1; return b; }

// Rotation gate on logical basis-bit p, in slot space.
// MASK = P^{-1} e_p (9-bit XOR pairing mask over slot index i = lane<<4 | j)
// ROLE = row_p(P): side of slot i = parity(ROLE & i); side 0 uses (m00,m01), side 1 (m11,m10).
template<int MASK, int ROLE>
__device__ __forceinline__ void apply_gate(float (&re)[16], float (&im)[16],
                                           const float* __restrict__ M, int lane) {
    constexpr int ml = MASK & 0xF;          // register part of pairing mask
    constexpr int mw = (MASK >> 4) & 0x1F;  // lane part of pairing mask
    const int lp = __popc((ROLE >> 4) & lane) & 1;

    const float m00r = M[0], m00i = M[1], m01r = M[2], m01i = M[3];
    const float m10r = M[4], m10i = M[5], m11r = M[6], m11i = M[7];
    // coefficient sets: element with reg-parity t has side = lp ^ t
    const float a0r = lp ? m11r : m00r, a0i = lp ? m11i : m00i;  // t=0 self
    const float a1r = lp ? m10r : m01r, a1i = lp ? m10i : m01i;  // t=0 partner
    const float b0r = lp ? m00r : m11r, b0i = lp ? m00i : m11i;  // t=1 self
    const float b1r = lp ? m01r : m10r, b1i = lp ? m01i : m10i;  // t=1 partner

    if constexpr (mw == 0) {
        constexpr int hb = msbbit(ml);
        #pragma unroll
        for (int j = 0; j < 16; ++j) {
            if ((j & hb) != 0) continue;
            const int k = j ^ ml;
            const int tj = __popc(ROLE & j) & 1;   // compile-time
            const int tk = __popc(ROLE & k) & 1;   // compile-time
            const float sr = re[j], si = im[j], pr = re[k], pi = im[k];
            {
                const float c0r = tj ? b0r : a0r, c0i = tj ? b0i : a0i;
                const float c1r = tj ? b1r : a1r, c1i = tj ? b1i : a1i;
                re[j] = c0r * sr - c0i * si + c1r * pr - c1i * pi;
                im[j] = c0r * si + c0i * sr + c1r * pi + c1i * pr;
            }
            {
                const float c0r = tk ? b0r : a0r, c0i = tk ? b0i : a0i;
                const float c1r = tk ? b1r : a1r, c1i = tk ? b1i : a1i;
                re[k] = c0r * pr - c0i * pi + c1r * sr - c1i * si;
                im[k] = c0r * pi + c0i * pr + c1r * si + c1i * sr;
            }
        }
    } else if constexpr (ml == 0) {
        #pragma unroll
        for (int j = 0; j < 16; ++j) {
            const float pr = __shfl_xor_sync(0xffffffffu, re[j], mw);
            const float pi = __shfl_xor_sync(0xffffffffu, im[j], mw);
            const int tj = __popc(ROLE & j) & 1;   // compile-time
            const float c0r = tj ? b0r : a0r, c0i = tj ? b0i : a0i;
            const float c1r = tj ? b1r : a1r, c1i = tj ? b1i : a1i;
            const float sr = re[j], si = im[j];
            re[j] = c0r * sr - c0i * si + c1r * pr - c1i * pi;
            im[j] = c0r * si + c0i * sr + c1r * pi + c1i * pr;
        }
    } else {
        constexpr int hb = msbbit(ml);
        #pragma unroll
        for (int j = 0; j < 16; ++j) {
            if ((j & hb) != 0) continue;
            const int k = j ^ ml;
            const float pjr = __shfl_xor_sync(0xffffffffu, re[k], mw);
            const float pji = __shfl_xor_sync(0xffffffffu, im[k], mw);
            const float pkr = __shfl_xor_sync(0xffffffffu, re[j], mw);
            const float pki = __shfl_xor_sync(0xffffffffu, im[j], mw);
            const int tj = __popc(ROLE & j) & 1;   // compile-time
            const int tk = __popc(ROLE & k) & 1;   // compile-time
            const float sjr = re[j], sji = im[j], skr = re[k], ski = im[k];
            {
                const float c0r = tj ? b0r : a0r, c0i = tj ? b0i : a0i;
                const float c1r = tj ? b1r : a1r, c1i = tj ? b1i : a1i;
                re[j] = c0r * sjr - c0i * sji + c1r * pjr - c1i * pji;
                im[j] = c0r * sji + c0i * sjr + c1r * pji + c1i * pjr;
            }
            {
                const float c0r = tk ? b0r : a0r, c0i = tk ? b0i : a0i;
                const float c1r = tk ? b1r : a1r, c1i = tk ? b1i : a1i;
                re[k] = c0r * skr - c0i * ski + c1r * pkr - c1i * pki;
                im[k] = c0r * ski + c0i * skr + c1r * pki + c1i * pkr;
            }
        }
    }
}

__global__ void __launch_bounds__(THREADS)
qlayer_kernel(const float* __restrict__ x, const float* __restrict__ wts,
              float* __restrict__ out, int nsamp) {
    // rotation matrices, shared across samples: smat[layer][qubit][m00r,m00i,m01r,m01i,m10r,m10i,m11r,m11i]
    __shared__ float smat[3][9][8];
    const int tid = threadIdx.x;
    if (tid < 27) {
        const int l = tid / 9, qb = tid % 9;
        const float phi = wts[(l * 9 + qb) * 3 + 0];
        const float th  = wts[(l * 9 + qb) * 3 + 1];
        const float om  = wts[(l * 9 + qb) * 3 + 2];
        float st, ct; sincosf(0.5f * th, &st, &ct);
        float sA, cA; sincosf(0.5f * (phi + om), &sA, &cA);
        float sB, cB; sincosf(0.5f * (phi - om), &sB, &cB);
        float* m = smat[l][qb];
        m[0] =  cA * ct;  m[1] = -sA * ct;   // m00 = e^{-i(phi+om)/2} cos(th/2)
        m[2] = -cB * st;  m[3] = -sB * st;   // m01 = -e^{+i(phi-om)/2} sin
        m[4] =  cB * st;  m[5] = -sB * st;   // m10 = e^{-i(phi-om)/2} sin
        m[6] =  cA * ct;  m[7] =  sA * ct;   // m11 = e^{+i(phi+om)/2} cos
    }
    __syncthreads();

    const int lane = tid & 31;
    const int warp = tid >> 5;
    const int b = blockIdx.x * WARPS_PER_BLOCK + warp;
    if (b >= nsamp) return;

    // --- per-qubit initial 2-vectors with layer-0 rotation folded in ---
    float v0r = 0.f, v0i = 0.f, v1r = 0.f, v1i = 0.f;
    if (lane < 9) {
        const float xv = x[b * 9 + lane];
        float s, c; sincosf(0.5f * xv, &s, &c);
        const float* m = smat[0][lane];
        // v = R0 @ [cos, -i sin]:  m01*(-i s) = (s*m01i, -s*m01r)
        v0r = m[0] * c + m[3] * s;
        v0i = m[1] * c - m[2] * s;
        v1r = m[4] * c + m[7] * s;
        v1i = m[5] * c - m[6] * s;
    }
    float w0r[9], w0i[9], w1r[9], w1i[9];
    #pragma unroll
    for (int q = 0; q < 9; ++q) {
        w0r[q] = __shfl_sync(0xffffffffu, v0r, q);
        w0i[q] = __shfl_sync(0xffffffffu, v0i, q);
        w1r[q] = __shfl_sync(0xffffffffu, v1r, q);
        w1i[q] = __shfl_sync(0xffffffffu, v1i, q);
    }

    // --- build product state: slot i = (lane<<4)|j; index bit p <-> qubit (8-p) ---
    float pr = 1.0f, pi = 0.0f;
    #pragma unroll
    for (int k = 0; k < 5; ++k) {           // lane bit k = index bit 4+k -> qubit 4-k
        const int q = 4 - k;
        const int bsel = (lane >> k) & 1;
        cmul(pr, pi, bsel ? w1r[q] : w0r[q], bsel ? w1i[q] : w0i[q]);
    }
    float re[16], im[16];
    {
        float c2r[2], c2i[2];
        #pragma unroll
        for (int b3 = 0; b3 < 2; ++b3) {    // j bit3 -> qubit 5
            c2r[b3] = pr; c2i[b3] = pi;
            cmul(c2r[b3], c2i[b3], b3 ? w1r[5] : w0r[5], b3 ? w1i[5] : w0i[5]);
        }
        float c4r[4], c4i[4];
        #pragma unroll
        for (int t = 0; t < 4; ++t) {       // j bit2 -> qubit 6
            const int hi = t >> 1, b2 = t & 1;
            c4r[t] = c2r[hi]; c4i[t] = c2i[hi];
            cmul(c4r[t], c4i[t], b2 ? w1r[6] : w0r[6], b2 ? w1i[6] : w0i[6]);
        }
        float c8r[8], c8i[8];
        #pragma unroll
        for (int t = 0; t < 8; ++t) {       // j bit1 -> qubit 7
            const int hi = t >> 1, b1 = t & 1;
            c8r[t] = c4r[hi]; c8i[t] = c4i[hi];
            cmul(c8r[t], c8i[t], b1 ? w1r[7] : w0r[7], b1 ? w1i[7] : w0i[7]);
        }
        #pragma unroll
        for (int j = 0; j < 16; ++j) {      // j bit0 -> qubit 8
            const int hi = j >> 1, b0 = j & 1;
            re[j] = c8r[hi]; im[j] = c8i[hi];
            cmul(re[j], im[j], b0 ? w1r[8] : w0r[8], b0 ? w1i[8] : w0i[8]);
        }
    }

    // --- layer-1 rotations (CNOT ring r=1 folded; P1 = A1) ---
    // gate on bit p: MASK = col p of A1^{-1}, ROLE = row p of A1, matrix qubit (8-p)
    apply_gate<0x181, 0x1FF>(re, im, smat[1][8], lane);  // p=0
    apply_gate<0x003, 0x1FE>(re, im, smat[1][7], lane);  // p=1
    apply_gate<0x006, 0x1FC>(re, im, smat[1][6], lane);  // p=2
    apply_gate<0x00C, 0x1F8>(re, im, smat[1][5], lane);  // p=3
    apply_gate<0x018, 0x1F0>(re, im, smat[1][4], lane);  // p=4
    apply_gate<0x030, 0x1E0>(re, im, smat[1][3], lane);  // p=5
    apply_gate<0x060, 0x1C0>(re, im, smat[1][2], lane);  // p=6
    apply_gate<0x0C0, 0x180>(re, im, smat[1][1], lane);  // p=7
    apply_gate<0x180, 0x0FF>(re, im, smat[1][0], lane);  // p=8

    // --- layer-2 rotations (CNOT rings r=1,2 folded; P2 = A2*A1) ---
    apply_gate<0x171, 0x0CC>(re, im, smat[2][8], lane);  // p=0
    apply_gate<0x1E3, 0x066>(re, im, smat[2][7], lane);  // p=1
    apply_gate<0x187, 0x133>(re, im, smat[2][6], lane);  // p=2
    apply_gate<0x00F, 0x198>(re, im, smat[2][5], lane);  // p=3
    apply_gate<0x01E, 0x0CF>(re, im, smat[2][4], lane);  // p=4
    apply_gate<0x03C, 0x060>(re, im, smat[2][3], lane);  // p=5
    apply_gate<0x078, 0x13F>(re, im, smat[2][2], lane);  // p=6
    apply_gate<0x0F0, 0x14C>(re, im, smat[2][1], lane);  // p=7
    apply_gate<0x1E0, 0x099>(re, im, smat[2][0], lane);  // p=8

    // --- probabilities + Z expectations (final CNOT ring r=3 folded into P3 rows) ---
    float prob[16];
    #pragma unroll
    for (int j = 0; j < 16; ++j) prob[j] = re[j] * re[j] + im[j] * im[j];

    // ZM[w] = row (8-w) of P3 = A3*A2*A1
    constexpr int ZM[9] = {0x153, 0x0A9, 0x154, 0x0F9, 0x183, 0x0A7, 0x1CA, 0x1E5, 0x06B};
    float acc[9];
    #pragma unroll
    for (int w = 0; w < 9; ++w) {
        const int zlo = ZM[w] & 0xF;
        float s = 0.f;
        #pragma unroll
        for (int j = 0; j < 16; ++j) {
            if (__popc(zlo & j) & 1) s -= prob[j]; else s += prob[j];  // compile-time sign
        }
        const int zhi = ZM[w] >> 4;
        acc[w] = (__popc(zhi & lane) & 1) ? -s : s;
    }
    #pragma unroll
    for (int w = 0; w < 9; ++w) {
        #pragma unroll
        for (int off = 16; off > 0; off >>= 1)
            acc[w] += __shfl_xor_sync(0xffffffffu, acc[w], off);
    }
    if (lane < 9) {
        float v = acc[0];
        #pragma unroll
        for (int w = 1; w < 9; ++w) if (lane == w) v = acc[w];
        out[b * 9 + lane] = v;
    }
}

extern "C" void kernel_launch(void* const* d_in, const int* in_sizes, int n_in,
                              void* d_out, int out_size) {
    const float* x   = (const float*)d_in[0];   // (32768, 9) float32
    const float* wts = (const float*)d_in[1];   // (3, 9, 3) float32
    float* out = (float*)d_out;                 // (32768, 9) float32
    const int nsamp = in_sizes[0] / 9;
    const int blocks = (nsamp + WARPS_PER_BLOCK - 1) / WARPS_PER_BLOCK;
    qlayer_kernel<<<blocks, THREADS>>>(x, wts, out, nsamp);
}

// round 8
// speedup vs baseline: 1.1760x; 1.1760x over previous
#include <cuda_runtime.h>
#include <cuda_bf16.h>

#define WARPS_PER_BLOCK 8
#define THREADS (WARPS_PER_BLOCK * 32)

typedef unsigned long long u64;

__host__ __device__ constexpr int msbbit(int v) { int b = 1; while (v >>= 1) b <<= 1; return b; }

__device__ __forceinline__ u64 pk(float lo, float hi) {
    u64 r; asm("mov.b64 %0, {%1, %2};" : "=l"(r) : "f"(lo), "f"(hi)); return r;
}
__device__ __forceinline__ void upk(u64 v, float& lo, float& hi) {
    asm("mov.b64 {%0, %1}, %2;" : "=f"(lo), "=f"(hi) : "l"(v));
}
__device__ __forceinline__ u64 swap64(u64 v) {
    u64 r;
    asm("{ .reg .b32 lo, hi; mov.b64 {lo, hi}, %1; mov.b64 %0, {hi, lo}; }"
        : "=l"(r) : "l"(v));
    return r;
}
__device__ __forceinline__ u64 fma2(u64 a, u64 b, u64 c) {
    u64 r; asm("fma.rn.f32x2 %0, %1, %2, %3;" : "=l"(r) : "l"(a), "l"(b), "l"(c)); return r;
}
__device__ __forceinline__ u64 mul2(u64 a, u64 b) {
    u64 r; asm("mul.rn.f32x2 %0, %1, %2;" : "=l"(r) : "l"(a), "l"(b)); return r;
}
__device__ __forceinline__ u64 neg64(u64 v) { return v ^ 0x8000000080000000ULL; }

__device__ __forceinline__ void cmul(float& ar, float& ai, float br, float bi) {
    float r = ar * br - ai * bi;
    float i = ar * bi + ai * br;
    ar = r; ai = i;
}

// Packed rotation gate on logical basis-bit p.
// MASK = P^{-1} e_p over slot index i = lane<<4 | j; ROLE = row_p(P).
// State packed over register bit0: RE[h] = (re[2h], re[2h+1]).
// Coefficients: a0 = m00, a1 = m01 (4 floats in M). Side1 set = (conj m00, -conj m01),
// so side flips signs of a0i and a1r only; lane-parity sign via one XOR, element-parity
// sign via compile-time pack/negpack choice.
template<int MASK, int ROLE>
__device__ __forceinline__ void gate_pk(u64 (&RE)[8], u64 (&IM)[8],
                                        const float* __restrict__ M, int lane) {
    constexpr int ml = MASK & 0xF;
    constexpr int mw = (MASK >> 4) & 0x1F;
    constexpr int mh = ml >> 1;
    constexpr bool odd = (ml & 1) != 0;
    constexpr bool alt = (ROLE & 1) != 0;   // element parity alternates within pack

    const float a0r = M[0], a0i = M[1], a1r = M[2], a1i = M[3];
    const unsigned sm = (unsigned)((__popc((ROLE >> 4) & lane) & 1)) << 31;
    const float p0i = __uint_as_float(__float_as_uint(a0i) ^ sm);
    const float p1r = __uint_as_float(__float_as_uint(a1r) ^ sm);

    const u64 A0R = pk(a0r, a0r);
    const u64 U   = alt ? pk(p0i, -p0i) : pk(p0i, p0i);
    const u64 nU  = neg64(U);
    const u64 V   = alt ? pk(p1r, -p1r) : pk(p1r, p1r);
    const u64 nV  = neg64(V);
    const u64 W   = pk(a1i, a1i);
    const u64 nW  = neg64(W);

    // butterfly: T0 = element-parity of j=2h (compile-time constant after unroll)
    // re = a0r*sr - (-1)^t p0i*si + (-1)^t p1r*pr - a1i*pi
    // im = a0r*si + (-1)^t p0i*sr + (-1)^t p1r*pi + a1i*pr
    auto bfly = [&](bool T0, u64 sre, u64 sim, u64 pre, u64 pim, u64& ore, u64& oim) {
        ore = fma2(A0R, sre, fma2(T0 ? U : nU, sim, fma2(T0 ? nV : V, pre, mul2(nW, pim))));
        oim = fma2(A0R, sim, fma2(T0 ? nU : U, sre, fma2(T0 ? nV : V, pim, mul2(W, pre))));
    };

    if constexpr (mw == 0) {
        if constexpr (mh == 0) {
            // ml == 1: partner = swap within own pack
            #pragma unroll
            for (int h = 0; h < 8; ++h) {
                const bool T0 = (__popc(ROLE & (2 * h)) & 1) != 0;
                const u64 pre = swap64(RE[h]), pim = swap64(IM[h]);
                u64 nr, ni; bfly(T0, RE[h], IM[h], pre, pim, nr, ni);
                RE[h] = nr; IM[h] = ni;
            }
        } else {
            constexpr int hb = msbbit(mh);
            #pragma unroll
            for (int h = 0; h < 8; ++h) {
                if ((h & hb) != 0) continue;
                const int g = h ^ mh;
                const bool Th = (__popc(ROLE & (2 * h)) & 1) != 0;
                const bool Tg = (__popc(ROLE & (2 * g)) & 1) != 0;
                u64 prh = RE[g], pih = IM[g], prg = RE[h], pig = IM[h];
                if constexpr (odd) { prh = swap64(prh); pih = swap64(pih);
                                     prg = swap64(prg); pig = swap64(pig); }
                u64 nrh, nih, nrg, nig;
                bfly(Th, RE[h], IM[h], prh, pih, nrh, nih);
                bfly(Tg, RE[g], IM[g], prg, pig, nrg, nig);
                RE[h] = nrh; IM[h] = nih; RE[g] = nrg; IM[g] = nig;
            }
        }
    } else {
        if constexpr (mh == 0) {
            #pragma unroll
            for (int h = 0; h < 8; ++h) {
                u64 pre = __shfl_xor_sync(0xffffffffu, RE[h], mw);
                u64 pim = __shfl_xor_sync(0xffffffffu, IM[h], mw);
                if constexpr (odd) { pre = swap64(pre); pim = swap64(pim); }
                const bool T0 = (__popc(ROLE & (2 * h)) & 1) != 0;
                u64 nr, ni; bfly(T0, RE[h], IM[h], pre, pim, nr, ni);
                RE[h] = nr; IM[h] = ni;
            }
        } else {
            constexpr int hb = msbbit(mh);
            #pragma unroll
            for (int h = 0; h < 8; ++h) {
                if ((h & hb) != 0) continue;
                const int g = h ^ mh;
                const bool Th = (__popc(ROLE & (2 * h)) & 1) != 0;
                const bool Tg = (__popc(ROLE & (2 * g)) & 1) != 0;
                u64 prh = __shfl_xor_sync(0xffffffffu, RE[g], mw);
                u64 pih = __shfl_xor_sync(0xffffffffu, IM[g], mw);
                u64 prg = __shfl_xor_sync(0xffffffffu, RE[h], mw);
                u64 pig = __shfl_xor_sync(0xffffffffu, IM[h], mw);
                if constexpr (odd) { prh = swap64(prh); pih = swap64(pih);
                                     prg = swap64(prg); pig = swap64(pig); }
                u64 nrh, nih, nrg, nig;
                bfly(Th, RE[h], IM[h], prh, pih, nrh, nih);
                bfly(Tg, RE[g], IM[g], prg, pig, nrg, nig);
                RE[h] = nrh; IM[h] = nih; RE[g] = nrg; IM[g] = nig;
            }
        }
    }
}

__device__ __forceinline__ float laneWHT(float v, unsigned s0, unsigned s1, unsigned s2,
                                         unsigned s3, unsigned s4) {
    float t;
    t = __shfl_xor_sync(0xffffffffu, v, 1);  v = t + __uint_as_float(__float_as_uint(v) ^ s0);
    t = __shfl_xor_sync(0xffffffffu, v, 2);  v = t + __uint_as_float(__float_as_uint(v) ^ s1);
    t = __shfl_xor_sync(0xffffffffu, v, 4);  v = t + __uint_as_float(__float_as_uint(v) ^ s2);
    t = __shfl_xor_sync(0xffffffffu, v, 8);  v = t + __uint_as_float(__float_as_uint(v) ^ s3);
    t = __shfl_xor_sync(0xffffffffu, v, 16); v = t + __uint_as_float(__float_as_uint(v) ^ s4);
    return v;
}

__global__ void __launch_bounds__(THREADS)
qlayer_kernel(const float* __restrict__ x, const float* __restrict__ wts,
              float* __restrict__ out, int nsamp) {
    // smat[l][q] = {m00r, m00i, m01r, m01i}  (m11 = conj m00, m10 = -conj m01)
    __shared__ float smat[3][9][4];
    const int tid = threadIdx.x;
    if (tid < 27) {
        const int l = tid / 9, qb = tid % 9;
        const float phi = wts[(l * 9 + qb) * 3 + 0];
        const float th  = wts[(l * 9 + qb) * 3 + 1];
        const float om  = wts[(l * 9 + qb) * 3 + 2];
        float st, ct; sincosf(0.5f * th, &st, &ct);
        float sA, cA; sincosf(0.5f * (phi + om), &sA, &cA);
        float sB, cB; sincosf(0.5f * (phi - om), &sB, &cB);
        float* m = smat[l][qb];
        m[0] =  cA * ct;   // m00r
        m[1] = -sA * ct;   // m00i
        m[2] = -cB * st;   // m01r
        m[3] = -sB * st;   // m01i
    }
    __syncthreads();

    const int lane = tid & 31;
    const int warp = tid >> 5;
    const int b = blockIdx.x * WARPS_PER_BLOCK + warp;
    if (b >= nsamp) return;

    // --- per-qubit initial 2-vectors with layer-0 rotation folded in ---
    float v0r = 0.f, v0i = 0.f, v1r = 0.f, v1i = 0.f;
    if (lane < 9) {
        const float xv = x[b * 9 + lane];
        float s, c; sincosf(0.5f * xv, &s, &c);
        const float* m = smat[0][lane];
        const float a0r = m[0], a0i = m[1], a1r = m[2], a1i = m[3];
        // v = R0 @ [cos, -i sin]
        v0r =  a0r * c + a1i * s;
        v0i =  a0i * c - a1r * s;
        v1r = -a1r * c - a0i * s;   // m10r*c + m11i*s
        v1i =  a1i * c - a0r * s;   // m10i*c - m11r*s
    }
    float w0r[9], w0i[9], w1r[9], w1i[9];
    #pragma unroll
    for (int q = 0; q < 9; ++q) {
        w0r[q] = __shfl_sync(0xffffffffu, v0r, q);
        w0i[q] = __shfl_sync(0xffffffffu, v0i, q);
        w1r[q] = __shfl_sync(0xffffffffu, v1r, q);
        w1i[q] = __shfl_sync(0xffffffffu, v1i, q);
    }

    // --- build product state (scalar), slot i = (lane<<4)|j; index bit p <-> qubit (8-p) ---
    float prd = 1.0f, pid = 0.0f;
    #pragma unroll
    for (int k = 0; k < 5; ++k) {
        const int q = 4 - k;
        const int bsel = (lane >> k) & 1;
        cmul(prd, pid, bsel ? w1r[q] : w0r[q], bsel ? w1i[q] : w0i[q]);
    }
    float re[16], im[16];
    {
        float c2r[2], c2i[2];
        #pragma unroll
        for (int b3 = 0; b3 < 2; ++b3) {
            c2r[b3] = prd; c2i[b3] = pid;
            cmul(c2r[b3], c2i[b3], b3 ? w1r[5] : w0r[5], b3 ? w1i[5] : w0i[5]);
        }
        float c4r[4], c4i[4];
        #pragma unroll
        for (int t = 0; t < 4; ++t) {
            const int hi = t >> 1, b2 = t & 1;
            c4r[t] = c2r[hi]; c4i[t] = c2i[hi];
            cmul(c4r[t], c4i[t], b2 ? w1r[6] : w0r[6], b2 ? w1i[6] : w0i[6]);
        }
        float c8r[8], c8i[8];
        #pragma unroll
        for (int t = 0; t < 8; ++t) {
            const int hi = t >> 1, b1 = t & 1;
            c8r[t] = c4r[hi]; c8i[t] = c4i[hi];
            cmul(c8r[t], c8i[t], b1 ? w1r[7] : w0r[7], b1 ? w1i[7] : w0i[7]);
        }
        #pragma unroll
        for (int j = 0; j < 16; ++j) {
            const int hi = j >> 1, b0 = j & 1;
            re[j] = c8r[hi]; im[j] = c8i[hi];
            cmul(re[j], im[j], b0 ? w1r[8] : w0r[8], b0 ? w1i[8] : w0i[8]);
        }
    }
    // pack over register bit0
    u64 RE[8], IM[8];
    #pragma unroll
    for (int h = 0; h < 8; ++h) {
        RE[h] = pk(re[2 * h], re[2 * h + 1]);
        IM[h] = pk(im[2 * h], im[2 * h + 1]);
    }

    // --- layer-1 rotations (CNOT ring r=1 folded; P1 = A1) ---
    gate_pk<0x181, 0x1FF>(RE, IM, smat[1][8], lane);  // p=0
    gate_pk<0x003, 0x1FE>(RE, IM, smat[1][7], lane);  // p=1
    gate_pk<0x006, 0x1FC>(RE, IM, smat[1][6], lane);  // p=2
    gate_pk<0x00C, 0x1F8>(RE, IM, smat[1][5], lane);  // p=3
    gate_pk<0x018, 0x1F0>(RE, IM, smat[1][4], lane);  // p=4
    gate_pk<0x030, 0x1E0>(RE, IM, smat[1][3], lane);  // p=5
    gate_pk<0x060, 0x1C0>(RE, IM, smat[1][2], lane);  // p=6
    gate_pk<0x0C0, 0x180>(RE, IM, smat[1][1], lane);  // p=7
    gate_pk<0x180, 0x0FF>(RE, IM, smat[1][0], lane);  // p=8

    // --- layer-2 rotations (CNOT rings r=1,2 folded; P2 = A2*A1) ---
    gate_pk<0x171, 0x0CC>(RE, IM, smat[2][8], lane);  // p=0
    gate_pk<0x1E3, 0x066>(RE, IM, smat[2][7], lane);  // p=1
    gate_pk<0x187, 0x133>(RE, IM, smat[2][6], lane);  // p=2
    gate_pk<0x00F, 0x198>(RE, IM, smat[2][5], lane);  // p=3
    gate_pk<0x01E, 0x0CF>(RE, IM, smat[2][4], lane);  // p=4
    gate_pk<0x03C, 0x060>(RE, IM, smat[2][3], lane);  // p=5
    gate_pk<0x078, 0x13F>(RE, IM, smat[2][2], lane);  // p=6
    gate_pk<0x0F0, 0x14C>(RE, IM, smat[2][1], lane);  // p=7
    gate_pk<0x1E0, 0x099>(RE, IM, smat[2][0], lane);  // p=8

    // --- probabilities (packed), then Walsh-Hadamard over register index ---
    float prob[16];
    #pragma unroll
    for (int h = 0; h < 8; ++h) {
        const u64 P = fma2(IM[h], IM[h], mul2(RE[h], RE[h]));
        upk(P, prob[2 * h], prob[2 * h + 1]);
    }
    #pragma unroll
    for (int bb = 0; bb < 4; ++bb) {
        const int mk = 1 << bb;
        #pragma unroll
        for (int j = 0; j < 16; ++j) {
            if ((j & mk) != 0) continue;
            const float u = prob[j], v = prob[j | mk];
            prob[j] = u + v; prob[j | mk] = u - v;
        }
    }
    // prob[z] = sum_j (-1)^{popc(z&j)} |psi|^2  for this lane

    // --- lane-side WHTs: one per distinct zlo; ZM[w] = row (8-w) of P3 = A3*A2*A1 ---
    // (zlo, zhi): w0:(3,0x15) w1:(9,0x0A) w2:(4,0x15) w3:(9,0x0F) w4:(3,0x18)
    //             w5:(7,0x0A) w6:(A,0x1C) w7:(5,0x1E) w8:(B,0x06)
    const unsigned s0 = (unsigned)( lane       & 1) << 31;
    const unsigned s1 = (unsigned)((lane >> 1) & 1) << 31;
    const unsigned s2 = (unsigned)((lane >> 2) & 1) << 31;
    const unsigned s3 = (unsigned)((lane >> 3) & 1) << 31;
    const unsigned s4 = (unsigned)((lane >> 4) & 1) << 31;
    const float S3 = laneWHT(prob[0x3], s0, s1, s2, s3, s4);
    const float S9 = laneWHT(prob[0x9], s0, s1, s2, s3, s4);
    const float S4 = laneWHT(prob[0x4], s0, s1, s2, s3, s4);
    const float S7 = laneWHT(prob[0x7], s0, s1, s2, s3, s4);
    const float SA = laneWHT(prob[0xA], s0, s1, s2, s3, s4);
    const float S5 = laneWHT(prob[0x5], s0, s1, s2, s3, s4);
    const float SB = laneWHT(prob[0xB], s0, s1, s2, s3, s4);

    const float r0 = __shfl_sync(0xffffffffu, S3, 0x15);
    const float r1 = __shfl_sync(0xffffffffu, S9, 0x0A);
    const float r2 = __shfl_sync(0xffffffffu, S4, 0x15);
    const float r3 = __shfl_sync(0xffffffffu, S9, 0x0F);
    const float r4 = __shfl_sync(0xffffffffu, S3, 0x18);
    const float r5 = __shfl_sync(0xffffffffu, S7, 0x0A);
    const float r6 = __shfl_sync(0xffffffffu, SA, 0x1C);
    const float r7 = __shfl_sync(0xffffffffu, S5, 0x1E);
    const float r8 = __shfl_sync(0xffffffffu, SB, 0x06);

    if (lane < 9) {
        float v = r0;
        if (lane == 1) v = r1;
        if (lane == 2) v = r2;
        if (lane == 3) v = r3;
        if (lane == 4) v = r4;
        if (lane == 5) v = r5;
        if (lane == 6) v = r6;
        if (lane == 7) v = r7;
        if (lane == 8) v = r8;
        out[b * 9 + lane] = v;
    }
}

extern "C" void kernel_launch(void* const* d_in, const int* in_sizes, int n_in,
                              void* d_out, int out_size) {
    const float* x   = (const float*)d_in[0];   // (32768, 9) float32
    const float* wts = (const float*)d_in[1];   // (3, 9, 3) float32
    float* out = (float*)d_out;                 // (32768, 9) float32
    const int nsamp = in_sizes[0] / 9;
    const int blocks = (nsamp + WARPS_PER_BLOCK - 1) / WARPS_PER_BLOCK;
    qlayer_kernel<<<blocks, THREADS>>>(x, wts, out, nsamp);
}

// round 9
// speedup vs baseline: 1.4567x; 1.2388x over previous
#include <cuda_runtime.h>
#include <cuda_bf16.h>

#define WARPS_PER_BLOCK 8
#define THREADS 256

typedef unsigned long long u64;

__host__ __device__ constexpr int msbbit(int v) { int b = 1; while (v >>= 1) b <<= 1; return b; }

__device__ __forceinline__ u64 pk(float lo, float hi) {
    u64 r; asm("mov.b64 %0, {%1, %2};" : "=l"(r) : "f"(lo), "f"(hi)); return r;
}
__device__ __forceinline__ void upk(u64 v, float& lo, float& hi) {
    asm("mov.b64 {%0, %1}, %2;" : "=f"(lo), "=f"(hi) : "l"(v));
}
__device__ __forceinline__ u64 swap64(u64 v) {
    u64 r;
    asm("{ .reg .b32 lo, hi; mov.b64 {lo, hi}, %1; mov.b64 %0, {hi, lo}; }"
        : "=l"(r) : "l"(v));
    return r;
}
__device__ __forceinline__ u64 fma2(u64 a, u64 b, u64 c) {
    u64 r; asm("fma.rn.f32x2 %0, %1, %2, %3;" : "=l"(r) : "l"(a), "l"(b), "l"(c)); return r;
}
__device__ __forceinline__ u64 mul2(u64 a, u64 b) {
    u64 r; asm("mul.rn.f32x2 %0, %1, %2;" : "=l"(r) : "l"(a), "l"(b)); return r;
}
__device__ __forceinline__ u64 neg64(u64 v) { return v ^ 0x8000000080000000ULL; }

__device__ __forceinline__ void cmul(float& ar, float& ai, float br, float bi) {
    float r = ar * br - ai * bi;
    float i = ar * bi + ai * br;
    ar = r; ai = i;
}

// Real Ry gate on logical bit p in validated frame machinery.
// MASK = pairing mask over slot i = lane<<4|j ; ROLE = side mask (side = parity(ROLE&i)).
// side0 row = (ct, -st), side1 row = (ct, +st). State packed over register bit0.
template<int MASK, int ROLE>
__device__ __forceinline__ void gate_y(u64 (&RE)[8], u64 (&IM)[8],
                                       float ct, float st, int lane) {
    constexpr int ml = MASK & 0xF;
    constexpr int mw = (MASK >> 4) & 0x1F;
    constexpr int mh = ml >> 1;
    constexpr bool odd = (ml & 1) != 0;
    constexpr bool alt = (ROLE & 1) != 0;

    const int lp = __popc((ROLE >> 4) & lane) & 1;
    const float base = lp ? st : -st;          // coefficient of partner for reg-parity t=0
    const u64 C  = pk(ct, ct);
    const u64 SA = alt ? pk(base, -base) : pk(base, base);
    const u64 nSA = neg64(SA);

    // out = C*self + S_h*partner  (both components)
    if constexpr (mw == 0) {
        if constexpr (mh == 0) {
            // ml == 1: partner = swapped halves of own pack
            #pragma unroll
            for (int h = 0; h < 8; ++h) {
                const bool T0 = (__popc(ROLE & (2 * h)) & 1) != 0;
                const u64 S = T0 ? nSA : SA;
                const u64 pre = swap64(RE[h]), pim = swap64(IM[h]);
                RE[h] = fma2(C, RE[h], mul2(S, pre));
                IM[h] = fma2(C, IM[h], mul2(S, pim));
            }
        } else {
            constexpr int hb = msbbit(mh);
            #pragma unroll
            for (int h = 0; h < 8; ++h) {
                if ((h & hb) != 0) continue;
                const int g = h ^ mh;
                const bool Th = (__popc(ROLE & (2 * h)) & 1) != 0;
                const bool Tg = (__popc(ROLE & (2 * g)) & 1) != 0;
                const u64 Sh = Th ? nSA : SA;
                const u64 Sg = Tg ? nSA : SA;
                u64 prh = RE[g], pih = IM[g], prg = RE[h], pig = IM[h];
                if constexpr (odd) { prh = swap64(prh); pih = swap64(pih);
                                     prg = swap64(prg); pig = swap64(pig); }
                const u64 nrh = fma2(C, RE[h], mul2(Sh, prh));
                const u64 nih = fma2(C, IM[h], mul2(Sh, pih));
                const u64 nrg = fma2(C, RE[g], mul2(Sg, prg));
                const u64 nig = fma2(C, IM[g], mul2(Sg, pig));
                RE[h] = nrh; IM[h] = nih; RE[g] = nrg; IM[g] = nig;
            }
        }
    } else {
        if constexpr (mh == 0) {
            #pragma unroll
            for (int h = 0; h < 8; ++h) {
                u64 pre = __shfl_xor_sync(0xffffffffu, RE[h], mw);
                u64 pim = __shfl_xor_sync(0xffffffffu, IM[h], mw);
                if constexpr (odd) { pre = swap64(pre); pim = swap64(pim); }
                const bool T0 = (__popc(ROLE & (2 * h)) & 1) != 0;
                const u64 S = T0 ? nSA : SA;
                RE[h] = fma2(C, RE[h], mul2(S, pre));
                IM[h] = fma2(C, IM[h], mul2(S, pim));
            }
        } else {
            constexpr int hb = msbbit(mh);
            #pragma unroll
            for (int h = 0; h < 8; ++h) {
                if ((h & hb) != 0) continue;
                const int g = h ^ mh;
                const bool Th = (__popc(ROLE & (2 * h)) & 1) != 0;
                const bool Tg = (__popc(ROLE & (2 * g)) & 1) != 0;
                const u64 Sh = Th ? nSA : SA;
                const u64 Sg = Tg ? nSA : SA;
                u64 prh = __shfl_xor_sync(0xffffffffu, RE[g], mw);
                u64 pih = __shfl_xor_sync(0xffffffffu, IM[g], mw);
                u64 prg = __shfl_xor_sync(0xffffffffu, RE[h], mw);
                u64 pig = __shfl_xor_sync(0xffffffffu, IM[h], mw);
                if constexpr (odd) { prh = swap64(prh); pih = swap64(pih);
                                     prg = swap64(prg); pig = swap64(pig); }
                const u64 nrh = fma2(C, RE[h], mul2(Sh, prh));
                const u64 nih = fma2(C, IM[h], mul2(Sh, pih));
                const u64 nrg = fma2(C, RE[g], mul2(Sg, prg));
                const u64 nig = fma2(C, IM[g], mul2(Sg, pig));
                RE[h] = nrh; IM[h] = nih; RE[g] = nrg; IM[g] = nig;
            }
        }
    }
}

// state *= precomputed unit-modulus diagonal (packed), DR/DI indexed [h][lane]
__device__ __forceinline__ void apply_diag(u64 (&RE)[8], u64 (&IM)[8],
                                           const u64 (*__restrict__ DR)[32],
                                           const u64 (*__restrict__ DI)[32], int lane) {
    #pragma unroll
    for (int h = 0; h < 8; ++h) {
        const u64 dr = DR[h][lane], di = DI[h][lane];
        const u64 nre = fma2(IM[h], neg64(di), mul2(RE[h], dr));
        const u64 nim = fma2(IM[h], dr, mul2(RE[h], di));
        RE[h] = nre; IM[h] = nim;
    }
}

__device__ __forceinline__ float laneWHT(float v, unsigned s0, unsigned s1, unsigned s2,
                                         unsigned s3, unsigned s4) {
    float t;
    t = __shfl_xor_sync(0xffffffffu, v, 1);  v = t + __uint_as_float(__float_as_uint(v) ^ s0);
    t = __shfl_xor_sync(0xffffffffu, v, 2);  v = t + __uint_as_float(__float_as_uint(v) ^ s1);
    t = __shfl_xor_sync(0xffffffffu, v, 4);  v = t + __uint_as_float(__float_as_uint(v) ^ s2);
    t = __shfl_xor_sync(0xffffffffu, v, 8);  v = t + __uint_as_float(__float_as_uint(v) ^ s3);
    t = __shfl_xor_sync(0xffffffffu, v, 16); v = t + __uint_as_float(__float_as_uint(v) ^ s4);
    return v;
}

__global__ void __launch_bounds__(THREADS, 4)
qlayer_kernel(const float* __restrict__ x, const float* __restrict__ wts,
              float* __restrict__ out, int nsamp) {
    __shared__ float sw[81];            // staged weights
    __shared__ float s_m0[9][4];        // layer-0 full matrices {m00r,m00i,m01r,m01i}
    __shared__ float s_y[2][9][2];      // layers 1,2 Ry coeffs {ct, st}
    __shared__ u64 sDR[2][8][32];       // diagonals D_A (0), D_B (1): cos part, packed
    __shared__ u64 sDI[2][8][32];       //                              sin part

    const int tid = threadIdx.x;
    if (tid < 81) sw[tid] = wts[tid];
    __syncthreads();

    if (tid < 9) {
        const int qb = tid;
        const float phi = sw[qb * 3 + 0];
        const float th  = sw[qb * 3 + 1];
        const float om  = sw[qb * 3 + 2];
        float st, ct; sincosf(0.5f * th, &st, &ct);
        float sA, cA; sincosf(0.5f * (phi + om), &sA, &cA);
        float sB, cB; sincosf(0.5f * (phi - om), &sB, &cB);
        s_m0[qb][0] =  cA * ct;
        s_m0[qb][1] = -sA * ct;
        s_m0[qb][2] = -cB * st;
        s_m0[qb][3] = -sB * st;
    }
    if (tid < 18) {
        const int l = tid / 9 + 1, qb = tid % 9;
        float st, ct; sincosf(0.5f * sw[(l * 9 + qb) * 3 + 1], &st, &ct);
        s_y[l - 1][qb][0] = ct;
        s_y[l - 1][qb][1] = st;
    }
    {
        // diagonals: D_A = Z(phi1)^{P1}; D_B = Z(om1)^{P1} * Z(phi2)^{P2}.
        // slot side1 (parity(row&s)=1) -> e^{+i a/2}, side0 -> e^{-i a/2}.
        constexpr int R1[9] = {0x1FF,0x1FE,0x1FC,0x1F8,0x1F0,0x1E0,0x1C0,0x180,0x0FF};
        constexpr int R2[9] = {0x0CC,0x066,0x133,0x198,0x0CF,0x060,0x13F,0x14C,0x099};
        const int h = tid >> 5, ln = tid & 31;
        const int s0 = ln * 16 + 2 * h;
        float thA[2] = {0.f, 0.f}, thB[2] = {0.f, 0.f};
        #pragma unroll
        for (int p = 0; p < 9; ++p) {
            const int q = 8 - p;
            const float f1 = sw[(9 + q) * 3 + 0];    // phi, layer 1
            const float o1 = sw[(9 + q) * 3 + 2];    // omega, layer 1
            const float f2 = sw[(18 + q) * 3 + 0];   // phi, layer 2
            #pragma unroll
            for (int e = 0; e < 2; ++e) {
                const int s = s0 + e;
                const float g1 = (__popc(R1[p] & s) & 1) ? 0.5f : -0.5f;
                const float g2 = (__popc(R2[p] & s) & 1) ? 0.5f : -0.5f;
                thA[e] += g1 * f1;
                thB[e] += g1 * o1 + g2 * f2;
            }
        }
        float ca0, sa0, ca1, sa1, cb0, sb0, cb1, sb1;
        sincosf(thA[0], &sa0, &ca0); sincosf(thA[1], &sa1, &ca1);
        sincosf(thB[0], &sb0, &cb0); sincosf(thB[1], &sb1, &cb1);
        sDR[0][h][ln] = pk(ca0, ca1); sDI[0][h][ln] = pk(sa0, sa1);
        sDR[1][h][ln] = pk(cb0, cb1); sDI[1][h][ln] = pk(sb0, sb1);
    }
    __syncthreads();

    const int lane = tid & 31;
    const int warp = tid >> 5;
    const int b = blockIdx.x * WARPS_PER_BLOCK + warp;
    if (b >= nsamp) return;

    // --- per-qubit initial 2-vectors with full layer-0 rotation folded in ---
    float v0r = 0.f, v0i = 0.f, v1r = 0.f, v1i = 0.f;
    if (lane < 9) {
        const float xv = x[b * 9 + lane];
        float s, c; sincosf(0.5f * xv, &s, &c);
        const float a0r = s_m0[lane][0], a0i = s_m0[lane][1];
        const float a1r = s_m0[lane][2], a1i = s_m0[lane][3];
        v0r =  a0r * c + a1i * s;
        v0i =  a0i * c - a1r * s;
        v1r = -a1r * c - a0i * s;
        v1i =  a1i * c - a0r * s;
    }
    float w0r[9], w0i[9], w1r[9], w1i[9];
    #pragma unroll
    for (int q = 0; q < 9; ++q) {
        w0r[q] = __shfl_sync(0xffffffffu, v0r, q);
        w0i[q] = __shfl_sync(0xffffffffu, v0i, q);
        w1r[q] = __shfl_sync(0xffffffffu, v1r, q);
        w1i[q] = __shfl_sync(0xffffffffu, v1i, q);
    }

    // --- build product state: slot i = (lane<<4)|j; index bit p <-> qubit (8-p) ---
    float prd = 1.0f, pid = 0.0f;
    #pragma unroll
    for (int k = 0; k < 5; ++k) {
        const int q = 4 - k;
        const int bsel = (lane >> k) & 1;
        cmul(prd, pid, bsel ? w1r[q] : w0r[q], bsel ? w1i[q] : w0i[q]);
    }
    u64 RE[8], IM[8];
    {
        float c2r[2], c2i[2];
        #pragma unroll
        for (int b3 = 0; b3 < 2; ++b3) {
            c2r[b3] = prd; c2i[b3] = pid;
            cmul(c2r[b3], c2i[b3], b3 ? w1r[5] : w0r[5], b3 ? w1i[5] : w0i[5]);
        }
        float c4r[4], c4i[4];
        #pragma unroll
        for (int t = 0; t < 4; ++t) {
            const int hi = t >> 1, b2 = t & 1;
            c4r[t] = c2r[hi]; c4i[t] = c2i[hi];
            cmul(c4r[t], c4i[t], b2 ? w1r[6] : w0r[6], b2 ? w1i[6] : w0i[6]);
        }
        float c8r[8], c8i[8];
        #pragma unroll
        for (int t = 0; t < 8; ++t) {
            const int hi = t >> 1, b1 = t & 1;
            c8r[t] = c4r[hi]; c8i[t] = c4i[hi];
            cmul(c8r[t], c8i[t], b1 ? w1r[7] : w0r[7], b1 ? w1i[7] : w0i[7]);
        }
        // last level packed: pack halves select qubit-8 factor (w0, w1)
        const u64 W8R = pk(w0r[8], w1r[8]);
        const u64 W8I = pk(w0i[8], w1i[8]);
        const u64 nW8I = neg64(W8I);
        #pragma unroll
        for (int h = 0; h < 8; ++h) {
            const u64 CR = pk(c8r[h], c8r[h]);
            const u64 CI = pk(c8i[h], c8i[h]);
            RE[h] = fma2(CI, nW8I, mul2(CR, W8R));
            IM[h] = fma2(CI, W8R, mul2(CR, W8I));
        }
    }

    // --- D_A = Z(phi1) in P1 frame ---
    apply_diag(RE, IM, sDR[0], sDI[0], lane);

    // --- layer-1 Ry gates (P1 frame; gate p -> qubit 8-p) ---
    gate_y<0x181, 0x1FF>(RE, IM, s_y[0][8][0], s_y[0][8][1], lane);  // p=0
    gate_y<0x003, 0x1FE>(RE, IM, s_y[0][7][0], s_y[0][7][1], lane);  // p=1
    gate_y<0x006, 0x1FC>(RE, IM, s_y[0][6][0], s_y[0][6][1], lane);  // p=2
    gate_y<0x00C, 0x1F8>(RE, IM, s_y[0][5][0], s_y[0][5][1], lane);  // p=3
    gate_y<0x018, 0x1F0>(RE, IM, s_y[0][4][0], s_y[0][4][1], lane);  // p=4
    gate_y<0x030, 0x1E0>(RE, IM, s_y[0][3][0], s_y[0][3][1], lane);  // p=5
    gate_y<0x060, 0x1C0>(RE, IM, s_y[0][2][0], s_y[0][2][1], lane);  // p=6
    gate_y<0x0C0, 0x180>(RE, IM, s_y[0][1][0], s_y[0][1][1], lane);  // p=7
    gate_y<0x180, 0x0FF>(RE, IM, s_y[0][0][0], s_y[0][0][1], lane);  // p=8

    // --- D_B = Z(om1)^{P1} * Z(phi2)^{P2} ---
    apply_diag(RE, IM, sDR[1], sDI[1], lane);

    // --- layer-2 Ry gates (P2 frame) ---  [Z(om2) dropped: pure phase before |.|^2]
    gate_y<0x171, 0x0CC>(RE, IM, s_y[1][8][0], s_y[1][8][1], lane);  // p=0
    gate_y<0x1E3, 0x066>(RE, IM, s_y[1][7][0], s_y[1][7][1], lane);  // p=1
    gate_y<0x187, 0x133>(RE, IM, s_y[1][6][0], s_y[1][6][1], lane);  // p=2
    gate_y<0x00F, 0x198>(RE, IM, s_y[1][5][0], s_y[1][5][1], lane);  // p=3
    gate_y<0x01E, 0x0CF>(RE, IM, s_y[1][4][0], s_y[1][4][1], lane);  // p=4
    gate_y<0x03C, 0x060>(RE, IM, s_y[1][3][0], s_y[1][3][1], lane);  // p=5
    gate_y<0x078, 0x13F>(RE, IM, s_y[1][2][0], s_y[1][2][1], lane);  // p=6
    gate_y<0x0F0, 0x14C>(RE, IM, s_y[1][1][0], s_y[1][1][1], lane);  // p=7
    gate_y<0x1E0, 0x099>(RE, IM, s_y[1][0][0], s_y[1][0][1], lane);  // p=8

    // --- probabilities, register-side WHT ---
    float prob[16];
    #pragma unroll
    for (int h = 0; h < 8; ++h) {
        const u64 P = fma2(IM[h], IM[h], mul2(RE[h], RE[h]));
        upk(P, prob[2 * h], prob[2 * h + 1]);
    }
    #pragma unroll
    for (int bb = 0; bb < 4; ++bb) {
        const int mk = 1 << bb;
        #pragma unroll
        for (int j = 0; j < 16; ++j) {
            if ((j & mk) != 0) continue;
            const float u = prob[j], v = prob[j | mk];
            prob[j] = u + v; prob[j | mk] = u - v;
        }
    }

    // --- lane-side WHTs + broadcast picks; ZM rows of P3 ---
    const unsigned s0 = (unsigned)( lane       & 1) << 31;
    const unsigned s1 = (unsigned)((lane >> 1) & 1) << 31;
    const unsigned s2 = (unsigned)((lane >> 2) & 1) << 31;
    const unsigned s3 = (unsigned)((lane >> 3) & 1) << 31;
    const unsigned s4 = (unsigned)((lane >> 4) & 1) << 31;
    const float S3 = laneWHT(prob[0x3], s0, s1, s2, s3, s4);
    const float S9 = laneWHT(prob[0x9], s0, s1, s2, s3, s4);
    const float S4 = laneWHT(prob[0x4], s0, s1, s2, s3, s4);
    const float S7 = laneWHT(prob[0x7], s0, s1, s2, s3, s4);
    const float SA = laneWHT(prob[0xA], s0, s1, s2, s3, s4);
    const float S5 = laneWHT(prob[0x5], s0, s1, s2, s3, s4);
    const float SB = laneWHT(prob[0xB], s0, s1, s2, s3, s4);

    const float r0 = __shfl_sync(0xffffffffu, S3, 0x15);
    const float r1 = __shfl_sync(0xffffffffu, S9, 0x0A);
    const float r2 = __shfl_sync(0xffffffffu, S4, 0x15);
    const float r3 = __shfl_sync(0xffffffffu, S9, 0x0F);
    const float r4 = __shfl_sync(0xffffffffu, S3, 0x18);
    const float r5 = __shfl_sync(0xffffffffu, S7, 0x0A);
    const float r6 = __shfl_sync(0xffffffffu, SA, 0x1C);
    const float r7 = __shfl_sync(0xffffffffu, S5, 0x1E);
    const float r8 = __shfl_sync(0xffffffffu, SB, 0x06);

    if (lane < 9) {
        float v = r0;
        if (lane == 1) v = r1;
        if (lane == 2) v = r2;
        if (lane == 3) v = r3;
        if (lane == 4) v = r4;
        if (lane == 5) v = r5;
        if (lane == 6) v = r6;
        if (lane == 7) v = r7;
        if (lane == 8) v = r8;
        out[b * 9 + lane] = v;
    }
}

extern "C" void kernel_launch(void* const* d_in, const int* in_sizes, int n_in,
                              void* d_out, int out_size) {
    const float* x   = (const float*)d_in[0];   // (32768, 9) float32
    const float* wts = (const float*)d_in[1];   // (3, 9, 3) float32
    float* out = (float*)d_out;                 // (32768, 9) float32
    const int nsamp = in_sizes[0] / 9;
    const int blocks = (nsamp + WARPS_PER_BLOCK - 1) / WARPS_PER_BLOCK;
    qlayer_kernel<<<blocks, THREADS>>>(x, wts, out, nsamp);
}